// round 14
// baseline (speedup 1.0000x reference)
#include <cuda_runtime.h>
#include <cuda_fp16.h>
#include <cstddef>

__device__ float g_bufA[134217728];
__device__ float g_bufB[67108864];
__device__ float g_h[2097152];
__device__ uint4 g_wpack[11520];

__device__ __forceinline__ unsigned packh(float lo, float hi) {
    __half2 h = __floats2half2_rn(lo, hi);
    return *reinterpret_cast<unsigned*>(&h);
}

__device__ __forceinline__ void mma_f16(float* c,
                                        unsigned a0, unsigned a1, unsigned a2, unsigned a3,
                                        unsigned b0, unsigned b1) {
    asm volatile("mma.sync.aligned.m16n8k16.row.col.f32.f16.f16.f32 "
                 "{%0,%1,%2,%3}, {%4,%5,%6,%7}, {%8,%9}, {%0,%1,%2,%3};"
                 : "+f"(c[0]), "+f"(c[1]), "+f"(c[2]), "+f"(c[3])
                 : "r"(a0), "r"(a1), "r"(a2), "r"(a3), "r"(b0), "r"(b1));
}

__device__ __forceinline__ void cp_async4(unsigned dst, const void* src, bool ok) {
    int sz = ok ? 4 : 0;
    asm volatile("cp.async.ca.shared.global [%0], [%1], 4, %2;"
                 :: "r"(dst), "l"(src), "r"(sz));
}

__device__ __forceinline__ void cp_async16(unsigned dst, const void* src, bool ok) {
    int sz = ok ? 16 : 0;
    asm volatile("cp.async.cg.shared.global [%0], [%1], 16, %2;"
                 :: "r"(dst), "l"(src), "r"(sz));
}

// Weight prepack: per (group, chunk) blocks of WCNT uint4,
// e = (t*NPAIR + p)*32 + lane.  Offsets: e2:0 e3:576 d1:2880 d2:5184 k2:5760
// k3:8064 k4:10368.  NOTE: k2 packed for NT=8 (single CO group).
__global__ void prep_all_k(const float* __restrict__ we2, const float* __restrict__ we3,
                           const float* __restrict__ wd1, const float* __restrict__ wd2,
                           const float* __restrict__ wk2, const float* __restrict__ wk3,
                           const float* __restrict__ wk4, uint4* __restrict__ dst)
{
    int e = blockIdx.x * 256 + threadIdx.x;
    if (e >= 11520) return;
    const float* w; int CI, COT, NT; int rem = e;
    if (rem < 576)                   { w = we2; CI = 16; COT = 32; NT = 4; }
    else if ((rem -= 576)  < 2304)   { w = we3; CI = 32; COT = 64; NT = 4; }
    else if ((rem -= 2304) < 2304)   { w = wd1; CI = 64; COT = 32; NT = 4; }
    else if ((rem -= 2304) < 576)    { w = wd2; CI = 32; COT = 16; NT = 2; }
    else if ((rem -= 576)  < 2304)   { w = wk2; CI = 32; COT = 64; NT = 8; }
    else if ((rem -= 2304) < 2304)   { w = wk3; CI = 64; COT = 32; NT = 4; }
    else       { rem -= 2304;          w = wk4; CI = 32; COT = 25; NT = 4; }

    int NPAIR = NT / 2;
    int WCNT = 9 * NPAIR * 32;
    int NCH = CI / 16;
    int gch = rem / WCNT, r2 = rem % WCNT;
    int g = gch / NCH, ch = gch % NCH;
    int lane = r2 & 31, q = r2 >> 5;
    int p = q % NPAIR, t = q / NPAIR;
    int coa = g * NT * 8 + 2 * p * 8 + (lane >> 2);
    int cob = coa + 8;
    int ci0 = ch * 16 + (lane & 3) * 2;

    auto fetch = [&](int co, int ci) -> float {
        return (co < COT) ? w[(co * CI + ci) * 9 + t] : 0.f;
    };
    uint4 v;
    v.x = packh(fetch(coa, ci0),     fetch(coa, ci0 + 1));
    v.y = packh(fetch(coa, ci0 + 8), fetch(coa, ci0 + 9));
    v.z = packh(fetch(cob, ci0),     fetch(cob, ci0 + 1));
    v.w = packh(fetch(cob, ci0 + 8), fetch(cob, ci0 + 9));
    dst[e] = v;
}

// FP16 mma.sync 3x3 conv + ReLU. Pixel tile 32x8, warp w owns row w.
// 1-row per warp; ALL weights preloaded once. MINB controls CTAs/SM.
// Input: packed half2 channel-pairs [N][CI/2][H][W]; smem [8cp][10r][P40],
// ICH2=408 (mod32=24 -> conflict-free). PACKED: half2 out; FUSE: k4 tail.
template <int CI, int NT, int COT, int H, int W, bool PACKED, bool FUSE, int MINB>
__global__ __launch_bounds__(256, MINB)
void conv3x3_f16(const unsigned* __restrict__ in, const uint4* __restrict__ wp,
                 void* __restrict__ outv, const float* __restrict__ hres)
{
    constexpr int NCH = CI / 16;
    constexpr int PITCH = 40;
    constexpr int ICH2 = 408;
    constexpr int ISZ = 8 * ICH2;
    constexpr int NPAIR = NT / 2;
    constexpr int WCNT = 9 * NPAIR * 32;
    constexpr int WTOT = NCH * WCNT;
    constexpr int WIT = (WTOT + 255) / 256;
    constexpr int GROUPS = (COT + NT * 8 - 1) / (NT * 8);
    constexpr int ZP = 257;

    extern __shared__ unsigned smem_u[];
    unsigned* in_s = smem_u;
    uint4*    ws   = (uint4*)(smem_u + 2 * ISZ);

    const int tid  = threadIdx.x;
    const int lane = tid & 31;
    const int wrp  = tid >> 5;
    const int gx0  = blockIdx.x * 32;
    const int gy0  = blockIdx.y * 8;
    const int img  = blockIdx.z / GROUPS;
    const int grp  = blockIdx.z % GROUPS;

    const unsigned in_base = (unsigned)__cvta_generic_to_shared(in_s);
    const unsigned ws_base = (unsigned)__cvta_generic_to_shared(ws);

    auto fill = [&](int ch, int buf) {
        const unsigned* base = in + ((size_t)img * (CI / 2) + ch * 8) * H * W;
        const unsigned sbase = in_base + buf * (ISZ * 4);
#pragma unroll
        for (int j = 0; j < 3; ++j) {
            int idx = tid + j * 256;
            if (idx < 640) {
                int ci = idx / 80;
                int rem = idx % 80;
                int r = rem >> 3, seg = rem & 7;
                int gy = gy0 + r - 1;
                bool ok = (unsigned)gy < (unsigned)H;
                const unsigned* src = base + (size_t)ci * H * W
                                    + (ok ? gy : 0) * W + gx0 + seg * 4;
                cp_async16(sbase + (ci * ICH2 + r * PITCH + 4 + seg * 4) * 4, src, ok);
            }
        }
        if (tid < 160) {
            int ci = tid / 20;
            int rem = tid % 20;
            int r = rem >> 1, side = rem & 1;
            int gy = gy0 + r - 1;
            int gx = side ? gx0 + 32 : gx0 - 1;
            bool ok = ((unsigned)gy < (unsigned)H) && ((unsigned)gx < (unsigned)W);
            const unsigned* src = base + (size_t)ci * H * W + (ok ? gy * W + gx : 0);
            cp_async4(sbase + (ci * ICH2 + r * PITCH + (side ? 36 : 3)) * 4, src, ok);
        }
        asm volatile("cp.async.commit_group;");
    };

    {
        const uint4* wsrc = wp + (size_t)grp * WTOT;
#pragma unroll
        for (int j = 0; j < WIT; ++j) {
            int i = tid + j * 256;
            if (i < WTOT)
                cp_async16(ws_base + i * 16, wsrc + i, true);
        }
    }
    fill(0, 0);
    asm volatile("cp.async.wait_group 0;");
    __syncthreads();

    float acc[2][NT][4];
#pragma unroll
    for (int m = 0; m < 2; ++m)
#pragma unroll
        for (int n = 0; n < NT; ++n)
#pragma unroll
            for (int i = 0; i < 4; ++i) acc[m][n][i] = 0.f;

    const int arow = lane >> 2;
    const int aci  = lane & 3;

    for (int ch = 0; ch < NCH; ++ch) {
        const int buf = ch & 1;
        if (ch + 1 < NCH) fill(ch + 1, buf ^ 1);

        const unsigned* A = in_s + buf * ISZ;
        const uint4*    B = ws + ch * WCNT;
#pragma unroll
        for (int kh = 0; kh < 3; ++kh) {
#pragma unroll
            for (int kw = 0; kw < 3; ++kw) {
                const int t = kh * 3 + kw;
                const int off = (wrp + kh) * PITCH + 3 + kw + arow;
                unsigned a00 = A[aci * ICH2 + off];
                unsigned a01 = A[aci * ICH2 + off + 8];
                unsigned a02 = A[(aci + 4) * ICH2 + off];
                unsigned a03 = A[(aci + 4) * ICH2 + off + 8];
                unsigned a10 = A[aci * ICH2 + off + 16];
                unsigned a11 = A[aci * ICH2 + off + 24];
                unsigned a12 = A[(aci + 4) * ICH2 + off + 16];
                unsigned a13 = A[(aci + 4) * ICH2 + off + 24];
                const uint4* wb = B + t * NPAIR * 32 + lane;
#pragma unroll
                for (int p = 0; p < NPAIR; ++p) {
                    uint4 b = wb[p * 32];
                    mma_f16(acc[0][2 * p],     a00, a01, a02, a03, b.x, b.y);
                    mma_f16(acc[1][2 * p],     a10, a11, a12, a13, b.x, b.y);
                    mma_f16(acc[0][2 * p + 1], a00, a01, a02, a03, b.z, b.w);
                    mma_f16(acc[1][2 * p + 1], a10, a11, a12, a13, b.z, b.w);
                }
            }
        }

        if (ch + 1 < NCH) {
            asm volatile("cp.async.wait_group 0;");
            __syncthreads();
        }
    }

    if (FUSE) {
        // fused per-pixel 5x5 dynamic conv + residual (k4): z -> smem only
        __syncthreads();
        float* z_s = (float*)smem_u;          // [25][ZP]
        float* h_s = z_s + 25 * ZP;           // [12][36]

        const int y = wrp;
#pragma unroll
        for (int m = 0; m < 2; ++m) {
            const int xl = m * 16 + arow;
#pragma unroll
            for (int n = 0; n < NT; ++n) {
                const int coA = n * 8 + 2 * (lane & 3);
                float v0 = fmaxf(acc[m][n][0], 0.f);
                float v1 = fmaxf(acc[m][n][1], 0.f);
                float v2 = fmaxf(acc[m][n][2], 0.f);
                float v3 = fmaxf(acc[m][n][3], 0.f);
                if (coA < 25) {
                    z_s[coA * ZP + y * 32 + xl]     = v0;
                    z_s[coA * ZP + y * 32 + xl + 8] = v2;
                }
                if (coA + 1 < 25) {
                    z_s[(coA + 1) * ZP + y * 32 + xl]     = v1;
                    z_s[(coA + 1) * ZP + y * 32 + xl + 8] = v3;
                }
            }
        }
        const float* hp = hres + (size_t)img * H * W;
        for (int i = tid; i < 12 * 36; i += 256) {
            int r = i / 36, c = i % 36;
            int gy = gy0 + r - 2, gx = gx0 + c - 2;
            h_s[i] = ((unsigned)gy < (unsigned)H && (unsigned)gx < (unsigned)W)
                     ? hp[gy * W + gx] : 0.f;
        }
        __syncthreads();

        const int py = tid >> 5, px = tid & 31;
        float res = h_s[(py + 2) * 36 + px + 2];
#pragma unroll
        for (int j = 0; j < 25; ++j) {
            const int kwv = j / 5, khv = j % 5;
            res += h_s[(py + khv) * 36 + px + kwv] * z_s[j * ZP + py * 32 + px];
        }
        ((float*)outv)[(size_t)img * H * W + (size_t)(gy0 + py) * W + gx0 + px] = res;
        return;
    }

    const int y = gy0 + wrp;
#pragma unroll
    for (int m = 0; m < 2; ++m) {
        const int x0 = gx0 + m * 16 + arow;
#pragma unroll
        for (int n = 0; n < NT; ++n) {
            const int coA = grp * NT * 8 + n * 8 + 2 * (lane & 3);
            float v0 = fmaxf(acc[m][n][0], 0.f);
            float v1 = fmaxf(acc[m][n][1], 0.f);
            float v2 = fmaxf(acc[m][n][2], 0.f);
            float v3 = fmaxf(acc[m][n][3], 0.f);
            if (PACKED) {
                unsigned* o = (unsigned*)outv;
                unsigned* p = o + ((size_t)(img * (COT / 2) + (coA >> 1)) * H + y) * W;
                p[x0]     = packh(v0, v1);
                p[x0 + 8] = packh(v2, v3);
            } else {
                float* o = (float*)outv;
                if (coA < COT) {
                    float* p = o + ((size_t)(img * COT + coA) * H + y) * W;
                    p[x0]     = v0;
                    p[x0 + 8] = v2;
                }
                if (coA + 1 < COT) {
                    float* p = o + ((size_t)(img * COT + coA + 1) * H + y) * W;
                    p[x0]     = v1;
                    p[x0 + 8] = v3;
                }
            }
        }
    }
}

// fp32 3x3 conv + ReLU, CI=1 (e1, k1); writes packed half2 pairs.
template <int COT, int PX>
__global__ __launch_bounds__(256)
void conv3x3_c1_k(const float* __restrict__ in, const float* __restrict__ w,
                  unsigned* __restrict__ out, int H, int W, int CO)
{
    constexpr int TW = 32;
    constexpr int TH = 8 * PX;
    __shared__ float st[(TH + 2) * (TW + 2)];
    __shared__ float ws[COT * 9];

    const int tid = threadIdx.x;
    const int tx = tid & 31;
    const int ty = tid >> 5;

    const int groups = CO / COT;
    const int g  = blockIdx.z % groups;
    const int n  = blockIdx.z / groups;
    const int co0 = g * COT;

    if (tid < COT * 9) ws[tid] = w[co0 * 9 + tid];

    const int gx0 = blockIdx.x * TW;
    const int gy0 = blockIdx.y * TH;

    const float* ip = in + (size_t)n * H * W;
    for (int i = tid; i < (TH + 2) * (TW + 2); i += 256) {
        int r = i / (TW + 2), c = i % (TW + 2);
        int gy = gy0 + r - 1, gx = gx0 + c - 1;
        st[i] = (gy >= 0 && gy < H && gx >= 0 && gx < W) ? ip[gy * W + gx] : 0.f;
    }
    __syncthreads();

    const int r0 = ty * PX;
    float v[PX + 2][3];
#pragma unroll
    for (int dy = 0; dy < PX + 2; ++dy)
#pragma unroll
        for (int dx = 0; dx < 3; ++dx)
            v[dy][dx] = st[(r0 + dy) * (TW + 2) + tx + dx];

    float acc[PX][COT];
#pragma unroll
    for (int p = 0; p < PX; ++p)
#pragma unroll
        for (int c = 0; c < COT; ++c) acc[p][c] = 0.f;

#pragma unroll
    for (int c = 0; c < COT; ++c) {
        const float* wp2 = ws + c * 9;
#pragma unroll
        for (int kh = 0; kh < 3; ++kh)
#pragma unroll
            for (int kw = 0; kw < 3; ++kw) {
                float wv = wp2[kh * 3 + kw];
#pragma unroll
                for (int p = 0; p < PX; ++p)
                    acc[p][c] += v[p + kh][kw] * wv;
            }
    }

#pragma unroll
    for (int c = 0; c < COT; c += 2) {
        unsigned* op = out + ((size_t)(n * (CO / 2) + (co0 + c) / 2) * H + gy0 + r0) * W
                     + gx0 + tx;
#pragma unroll
        for (int p = 0; p < PX; ++p) {
            float a = fmaxf(acc[p][c], 0.f);
            float b = fmaxf(acc[p][c + 1], 0.f);
            op[(size_t)p * W] = packh(a, b);
        }
    }
}

__global__ void shuffle_relu_k(const float* __restrict__ in, float* __restrict__ out)
{
    int idx = blockIdx.x * blockDim.x + threadIdx.x;
    int x = idx & 1023;
    int y = (idx >> 10) & 1023;
    int n = idx >> 20;
    int c = ((y & 3) << 2) | (x & 3);
    int hh = y >> 2, ww = x >> 2;
    float v = in[(((size_t)(n * 16 + c) * 256) + hh) * 256 + ww];
    out[idx] = v > 0.f ? v : 0.f;
}

extern "C" void kernel_launch(void* const* d_in, const int* in_sizes, int n_in,
                              void* d_out, int out_size)
{
    const float* x   = (const float*)d_in[0];
    const float* we1 = (const float*)d_in[1];
    const float* we2 = (const float*)d_in[2];
    const float* we3 = (const float*)d_in[3];
    const float* wd1 = (const float*)d_in[4];
    const float* wd2 = (const float*)d_in[5];
    const float* wk1 = (const float*)d_in[6];
    const float* wk2 = (const float*)d_in[7];
    const float* wk3 = (const float*)d_in[8];
    const float* wk4 = (const float*)d_in[9];
    float* out = (float*)d_out;

    float *bufA, *bufB, *hbuf;
    uint4* wpack;
    cudaGetSymbolAddress((void**)&bufA, g_bufA);
    cudaGetSymbolAddress((void**)&bufB, g_bufB);
    cudaGetSymbolAddress((void**)&hbuf, g_h);
    cudaGetSymbolAddress((void**)&wpack, g_wpack);
    unsigned* hA = (unsigned*)bufA;
    unsigned* hB = (unsigned*)bufB;

    const int O_E2 = 0, O_E3 = 576, O_D1 = 2880, O_D2 = 5184;
    const int O_K2 = 5760, O_K3 = 8064, O_K4 = 10368;

    // smem = 26112 (input dbuf) + WTOT*16
    const int sm_ci16   = 26112 + 9216;    // 35328  (CI16 NT4)
    const int sm_ci32   = 26112 + 18432;   // 44544  (CI32 NT4)
    const int sm_ci64   = 26112 + 36864;   // 62976  (CI64 NT4)
    const int sm_d2     = 26112 + 9216;    // 35328  (CI32 NT2)
    const int sm_k2nt8  = 26112 + 36864;   // 62976  (CI32 NT8)

    cudaFuncSetAttribute(conv3x3_f16<16, 4, 32, 256, 256, true, false, 3>,
                         cudaFuncAttributeMaxDynamicSharedMemorySize, sm_ci16);
    cudaFuncSetAttribute(conv3x3_f16<32, 4, 64, 256, 256, true, false, 3>,
                         cudaFuncAttributeMaxDynamicSharedMemorySize, sm_ci32);
    cudaFuncSetAttribute(conv3x3_f16<64, 4, 32, 256, 256, true, false, 3>,
                         cudaFuncAttributeMaxDynamicSharedMemorySize, sm_ci64);
    cudaFuncSetAttribute(conv3x3_f16<32, 2, 16, 256, 256, false, false, 3>,
                         cudaFuncAttributeMaxDynamicSharedMemorySize, sm_d2);
    cudaFuncSetAttribute(conv3x3_f16<32, 8, 64, 1024, 1024, true, false, 3>,
                         cudaFuncAttributeMaxDynamicSharedMemorySize, sm_k2nt8);
    cudaFuncSetAttribute(conv3x3_f16<64, 4, 32, 1024, 1024, true, false, 3>,
                         cudaFuncAttributeMaxDynamicSharedMemorySize, sm_ci64);
    cudaFuncSetAttribute(conv3x3_f16<32, 4, 25, 1024, 1024, false, true, 3>,
                         cudaFuncAttributeMaxDynamicSharedMemorySize, sm_ci32);

    const dim3 blk(256);

    prep_all_k<<<45, blk>>>(we2, we3, wd1, wd2, wk2, wk3, wk4, wpack);

    // encoder / decoder @ 256x256 (N=2)
    conv3x3_c1_k<16, 4><<<dim3(8, 8, 2), blk>>>(x, we1, hA, 256, 256, 16);
    conv3x3_f16<16, 4, 32, 256, 256, true,  false, 3><<<dim3(8, 32, 2), blk, sm_ci16>>>(hA, wpack + O_E2, hB, nullptr);
    conv3x3_f16<32, 4, 64, 256, 256, true,  false, 3><<<dim3(8, 32, 4), blk, sm_ci32>>>(hB, wpack + O_E3, hA, nullptr);
    conv3x3_f16<64, 4, 32, 256, 256, true,  false, 3><<<dim3(8, 32, 2), blk, sm_ci64>>>(hA, wpack + O_D1, hB, nullptr);
    conv3x3_f16<32, 2, 16, 256, 256, false, false, 3><<<dim3(8, 32, 2), blk, sm_d2>>>(hB, wpack + O_D2, bufA, nullptr);

    // pixel shuffle + relu -> (2,1,1024,1024) fp32
    shuffle_relu_k<<<8192, 256>>>(bufA, hbuf);

    // kernel-prediction branch @ 1024x1024
    conv3x3_c1_k<16, 4><<<dim3(32, 32, 4), blk>>>(hbuf, wk1, hB, 1024, 1024, 32);
    // k2: NT=8 single group (1.5 wf/HMMA), grid z = 2 images
    conv3x3_f16<32, 8, 64, 1024, 1024, true,  false, 3><<<dim3(32, 128, 2), blk, sm_k2nt8>>>(hB, wpack + O_K2, hA, nullptr);
    conv3x3_f16<64, 4, 32, 1024, 1024, true,  false, 3><<<dim3(32, 128, 2), blk, sm_ci64>>>(hA, wpack + O_K3, hB, nullptr);
    // k4 + fused per-pixel 5x5 dynamic conv + residual -> d_out
    conv3x3_f16<32, 4, 25, 1024, 1024, false, true,  3><<<dim3(32, 128, 2), blk, sm_ci32>>>(hB, wpack + O_K4, out, hbuf);
}

// round 15
// speedup vs baseline: 1.1472x; 1.1472x over previous
#include <cuda_runtime.h>
#include <cuda_fp16.h>
#include <cstddef>

__device__ float g_bufA[134217728];
__device__ float g_bufB[67108864];
__device__ float g_h[2097152];
__device__ uint4 g_wpack[11520];

__device__ __forceinline__ unsigned packh(float lo, float hi) {
    __half2 h = __floats2half2_rn(lo, hi);
    return *reinterpret_cast<unsigned*>(&h);
}

__device__ __forceinline__ void mma_f16(float* c,
                                        unsigned a0, unsigned a1, unsigned a2, unsigned a3,
                                        unsigned b0, unsigned b1) {
    asm volatile("mma.sync.aligned.m16n8k16.row.col.f32.f16.f16.f32 "
                 "{%0,%1,%2,%3}, {%4,%5,%6,%7}, {%8,%9}, {%0,%1,%2,%3};"
                 : "+f"(c[0]), "+f"(c[1]), "+f"(c[2]), "+f"(c[3])
                 : "r"(a0), "r"(a1), "r"(a2), "r"(a3), "r"(b0), "r"(b1));
}

__device__ __forceinline__ void cp_async4(unsigned dst, const void* src, bool ok) {
    int sz = ok ? 4 : 0;
    asm volatile("cp.async.ca.shared.global [%0], [%1], 4, %2;"
                 :: "r"(dst), "l"(src), "r"(sz));
}

__device__ __forceinline__ void cp_async16(unsigned dst, const void* src, bool ok) {
    int sz = ok ? 16 : 0;
    asm volatile("cp.async.cg.shared.global [%0], [%1], 16, %2;"
                 :: "r"(dst), "l"(src), "r"(sz));
}

// Weight prepack: per (group, chunk) blocks of WCNT uint4,
// e = (t*NPAIR + p)*32 + lane.  Offsets: e2:0 e3:576 d1:2880 d2:5184 k2:5760
// k3:8064 k4:10368.  All NT=4 except d2 (NT=2).
__global__ void prep_all_k(const float* __restrict__ we2, const float* __restrict__ we3,
                           const float* __restrict__ wd1, const float* __restrict__ wd2,
                           const float* __restrict__ wk2, const float* __restrict__ wk3,
                           const float* __restrict__ wk4, uint4* __restrict__ dst)
{
    int e = blockIdx.x * 256 + threadIdx.x;
    if (e >= 11520) return;
    const float* w; int CI, COT, NT; int rem = e;
    if (rem < 576)                   { w = we2; CI = 16; COT = 32; NT = 4; }
    else if ((rem -= 576)  < 2304)   { w = we3; CI = 32; COT = 64; NT = 4; }
    else if ((rem -= 2304) < 2304)   { w = wd1; CI = 64; COT = 32; NT = 4; }
    else if ((rem -= 2304) < 576)    { w = wd2; CI = 32; COT = 16; NT = 2; }
    else if ((rem -= 576)  < 2304)   { w = wk2; CI = 32; COT = 64; NT = 4; }
    else if ((rem -= 2304) < 2304)   { w = wk3; CI = 64; COT = 32; NT = 4; }
    else       { rem -= 2304;          w = wk4; CI = 32; COT = 25; NT = 4; }

    int NPAIR = NT / 2;
    int WCNT = 9 * NPAIR * 32;
    int NCH = CI / 16;
    int gch = rem / WCNT, r2 = rem % WCNT;
    int g = gch / NCH, ch = gch % NCH;
    int lane = r2 & 31, q = r2 >> 5;
    int p = q % NPAIR, t = q / NPAIR;
    int coa = g * NT * 8 + 2 * p * 8 + (lane >> 2);
    int cob = coa + 8;
    int ci0 = ch * 16 + (lane & 3) * 2;

    auto fetch = [&](int co, int ci) -> float {
        return (co < COT) ? w[(co * CI + ci) * 9 + t] : 0.f;
    };
    uint4 v;
    v.x = packh(fetch(coa, ci0),     fetch(coa, ci0 + 1));
    v.y = packh(fetch(coa, ci0 + 8), fetch(coa, ci0 + 9));
    v.z = packh(fetch(cob, ci0),     fetch(cob, ci0 + 1));
    v.w = packh(fetch(cob, ci0 + 8), fetch(cob, ci0 + 9));
    dst[e] = v;
}

// FP16 mma.sync 3x3 conv + ReLU.  Pixel tile 32(x) x 16(y).
//   Block 256 thr (8 warps); warp w computes output rows w and w+8.
//   Per warp: 4 M-tiles (2 rows x 2 col-halves) x NT N-tiles; B fragments
//   reused across both rows (18 smem ops per 16 HMMA).
//   ALL weights preloaded to smem once (no per-chunk weight staging).
//   Input: packed half2 channel-pairs [N][CI/2][H][W], CI chunked by 16,
//   input double-buffered via cp.async.
//   Smem input: [8 cpair][18 rows][PITCH=40] half2, ICH2=728 (mod 32 = 24 =>
//   conflict-free A loads). Interior at col 4, halo at 3/36.
//   PACKED: half2-pair output; else planar fp32 (masked). FUSE: k4 tail.
template <int CI, int NT, int COT, int H, int W, bool PACKED, bool FUSE>
__global__ __launch_bounds__(256, 2)
void conv3x3_f16(const unsigned* __restrict__ in, const uint4* __restrict__ wp,
                 void* __restrict__ outv, const float* __restrict__ hres)
{
    constexpr int NCH = CI / 16;
    constexpr int PITCH = 40;
    constexpr int ICH2 = 728;
    constexpr int ISZ = 8 * ICH2;            // 5824 words per input buffer
    constexpr int NPAIR = NT / 2;
    constexpr int WCNT = 9 * NPAIR * 32;
    constexpr int WTOT = NCH * WCNT;
    constexpr int WIT = (WTOT + 255) / 256;
    constexpr int GROUPS = (COT + NT * 8 - 1) / (NT * 8);
    constexpr int ZP = 513;                  // FUSE z pitch (16*32+1)

    extern __shared__ unsigned smem_u[];
    unsigned* in_s = smem_u;                       // [2][ISZ]
    uint4*    ws   = (uint4*)(smem_u + 2 * ISZ);   // [NCH][WCNT], loaded once

    const int tid  = threadIdx.x;
    const int lane = tid & 31;
    const int wrp  = tid >> 5;
    const int gx0  = blockIdx.x * 32;
    const int gy0  = blockIdx.y * 16;
    const int img  = blockIdx.z / GROUPS;
    const int grp  = blockIdx.z % GROUPS;

    const unsigned in_base = (unsigned)__cvta_generic_to_shared(in_s);
    const unsigned ws_base = (unsigned)__cvta_generic_to_shared(ws);

    auto fill = [&](int ch, int buf) {
        const unsigned* base = in + ((size_t)img * (CI / 2) + ch * 8) * H * W;
        const unsigned sbase = in_base + buf * (ISZ * 4);
        // interior: 8 cpair x 18 rows x 8 segs(16B) = 1152
#pragma unroll
        for (int j = 0; j < 5; ++j) {
            int idx = tid + j * 256;
            if (idx < 1152) {
                int ci = idx / 144;
                int rem = idx % 144;
                int r = rem >> 3, seg = rem & 7;
                int gy = gy0 + r - 1;
                bool ok = (unsigned)gy < (unsigned)H;
                const unsigned* src = base + (size_t)ci * H * W
                                    + (ok ? gy : 0) * W + gx0 + seg * 4;
                cp_async16(sbase + (ci * ICH2 + r * PITCH + 4 + seg * 4) * 4, src, ok);
            }
        }
        // halo: 8 cpair x 18 rows x 2 sides = 288 scalar half2
#pragma unroll
        for (int j = 0; j < 2; ++j) {
            int idx = tid + j * 256;
            if (idx < 288) {
                int ci = idx / 36;
                int rem = idx % 36;
                int r = rem >> 1, side = rem & 1;
                int gy = gy0 + r - 1;
                int gx = side ? gx0 + 32 : gx0 - 1;
                bool ok = ((unsigned)gy < (unsigned)H) && ((unsigned)gx < (unsigned)W);
                const unsigned* src = base + (size_t)ci * H * W + (ok ? gy * W + gx : 0);
                cp_async4(sbase + (ci * ICH2 + r * PITCH + (side ? 36 : 3)) * 4, src, ok);
            }
        }
        asm volatile("cp.async.commit_group;");
    };

    // one-time weight preload (all chunks of this group)
    {
        const uint4* wsrc = wp + (size_t)grp * WTOT;
#pragma unroll
        for (int j = 0; j < WIT; ++j) {
            int i = tid + j * 256;
            if (i < WTOT)
                cp_async16(ws_base + i * 16, wsrc + i, true);
        }
    }
    fill(0, 0);
    asm volatile("cp.async.wait_group 0;");
    __syncthreads();

    float acc[2][2][NT][4];   // [row-half][col-half][ntile][frag]
#pragma unroll
    for (int mr = 0; mr < 2; ++mr)
#pragma unroll
        for (int m = 0; m < 2; ++m)
#pragma unroll
            for (int n = 0; n < NT; ++n)
#pragma unroll
                for (int i = 0; i < 4; ++i) acc[mr][m][n][i] = 0.f;

    const int arow = lane >> 2;
    const int aci  = lane & 3;

    for (int ch = 0; ch < NCH; ++ch) {
        const int buf = ch & 1;
        if (ch + 1 < NCH) fill(ch + 1, buf ^ 1);

        const unsigned* A = in_s + buf * ISZ;
        const uint4*    B = ws + ch * WCNT;
#pragma unroll
        for (int kh = 0; kh < 3; ++kh) {
#pragma unroll
            for (int kw = 0; kw < 3; ++kw) {
                const int t = kh * 3 + kw;
                const uint4* wb = B + t * NPAIR * 32 + lane;
#pragma unroll
                for (int mr = 0; mr < 2; ++mr) {
                    const int off = (wrp + mr * 8 + kh) * PITCH + 3 + kw + arow;
                    unsigned a00 = A[aci * ICH2 + off];
                    unsigned a01 = A[aci * ICH2 + off + 8];
                    unsigned a02 = A[(aci + 4) * ICH2 + off];
                    unsigned a03 = A[(aci + 4) * ICH2 + off + 8];
                    unsigned a10 = A[aci * ICH2 + off + 16];
                    unsigned a11 = A[aci * ICH2 + off + 24];
                    unsigned a12 = A[(aci + 4) * ICH2 + off + 16];
                    unsigned a13 = A[(aci + 4) * ICH2 + off + 24];
#pragma unroll
                    for (int p = 0; p < NPAIR; ++p) {
                        uint4 b = wb[p * 32];
                        mma_f16(acc[mr][0][2 * p],     a00, a01, a02, a03, b.x, b.y);
                        mma_f16(acc[mr][1][2 * p],     a10, a11, a12, a13, b.x, b.y);
                        mma_f16(acc[mr][0][2 * p + 1], a00, a01, a02, a03, b.z, b.w);
                        mma_f16(acc[mr][1][2 * p + 1], a10, a11, a12, a13, b.z, b.w);
                    }
                }
            }
        }

        if (ch + 1 < NCH) {
            asm volatile("cp.async.wait_group 0;");
            __syncthreads();
        }
    }

    if (FUSE) {
        // -------- fused per-pixel 5x5 dynamic conv + residual (k4) --------
        __syncthreads();
        float* z_s = (float*)smem_u;          // [25][ZP]
        float* h_s = z_s + 25 * ZP;           // [20][36]

#pragma unroll
        for (int mr = 0; mr < 2; ++mr) {
            const int y = wrp + mr * 8;
#pragma unroll
            for (int m = 0; m < 2; ++m) {
                const int xl = m * 16 + arow;
#pragma unroll
                for (int n = 0; n < NT; ++n) {
                    const int coA = n * 8 + 2 * (lane & 3);
                    float v0 = fmaxf(acc[mr][m][n][0], 0.f);
                    float v1 = fmaxf(acc[mr][m][n][1], 0.f);
                    float v2 = fmaxf(acc[mr][m][n][2], 0.f);
                    float v3 = fmaxf(acc[mr][m][n][3], 0.f);
                    if (coA < 25) {
                        z_s[coA * ZP + y * 32 + xl]     = v0;
                        z_s[coA * ZP + y * 32 + xl + 8] = v2;
                    }
                    if (coA + 1 < 25) {
                        z_s[(coA + 1) * ZP + y * 32 + xl]     = v1;
                        z_s[(coA + 1) * ZP + y * 32 + xl + 8] = v3;
                    }
                }
            }
        }
        const float* hp = hres + (size_t)img * H * W;
        for (int i = tid; i < 20 * 36; i += 256) {
            int r = i / 36, c = i % 36;
            int gy = gy0 + r - 2, gx = gx0 + c - 2;
            h_s[i] = ((unsigned)gy < (unsigned)H && (unsigned)gx < (unsigned)W)
                     ? hp[gy * W + gx] : 0.f;
        }
        __syncthreads();

        const int py = tid >> 5, px = tid & 31;
        float* o = (float*)outv;
#pragma unroll
        for (int mr = 0; mr < 2; ++mr) {
            const int yy = py + mr * 8;
            float res = h_s[(yy + 2) * 36 + px + 2];
#pragma unroll
            for (int j = 0; j < 25; ++j) {
                const int kwv = j / 5, khv = j % 5;
                res += h_s[(yy + khv) * 36 + px + kwv] * z_s[j * ZP + yy * 32 + px];
            }
            o[(size_t)img * H * W + (size_t)(gy0 + yy) * W + gx0 + px] = res;
        }
        return;
    }

    // ---- epilogue: ReLU + store ----
#pragma unroll
    for (int mr = 0; mr < 2; ++mr) {
        const int y = gy0 + wrp + mr * 8;
#pragma unroll
        for (int m = 0; m < 2; ++m) {
            const int x0 = gx0 + m * 16 + arow;
#pragma unroll
            for (int n = 0; n < NT; ++n) {
                const int coA = grp * NT * 8 + n * 8 + 2 * (lane & 3);
                float v0 = fmaxf(acc[mr][m][n][0], 0.f);
                float v1 = fmaxf(acc[mr][m][n][1], 0.f);
                float v2 = fmaxf(acc[mr][m][n][2], 0.f);
                float v3 = fmaxf(acc[mr][m][n][3], 0.f);
                if (PACKED) {
                    unsigned* o = (unsigned*)outv;
                    unsigned* p = o + ((size_t)(img * (COT / 2) + (coA >> 1)) * H + y) * W;
                    p[x0]     = packh(v0, v1);
                    p[x0 + 8] = packh(v2, v3);
                } else {
                    float* o = (float*)outv;
                    if (coA < COT) {
                        float* p = o + ((size_t)(img * COT + coA) * H + y) * W;
                        p[x0]     = v0;
                        p[x0 + 8] = v2;
                    }
                    if (coA + 1 < COT) {
                        float* p = o + ((size_t)(img * COT + coA + 1) * H + y) * W;
                        p[x0]     = v1;
                        p[x0 + 8] = v3;
                    }
                }
            }
        }
    }
}

// fp32 3x3 conv + ReLU, CI=1 (e1, k1); writes packed half2 pairs.
template <int COT, int PX>
__global__ __launch_bounds__(256)
void conv3x3_c1_k(const float* __restrict__ in, const float* __restrict__ w,
                  unsigned* __restrict__ out, int H, int W, int CO)
{
    constexpr int TW = 32;
    constexpr int TH = 8 * PX;
    __shared__ float st[(TH + 2) * (TW + 2)];
    __shared__ float ws[COT * 9];

    const int tid = threadIdx.x;
    const int tx = tid & 31;
    const int ty = tid >> 5;

    const int groups = CO / COT;
    const int g  = blockIdx.z % groups;
    const int n  = blockIdx.z / groups;
    const int co0 = g * COT;

    if (tid < COT * 9) ws[tid] = w[co0 * 9 + tid];

    const int gx0 = blockIdx.x * TW;
    const int gy0 = blockIdx.y * TH;

    const float* ip = in + (size_t)n * H * W;
    for (int i = tid; i < (TH + 2) * (TW + 2); i += 256) {
        int r = i / (TW + 2), c = i % (TW + 2);
        int gy = gy0 + r - 1, gx = gx0 + c - 1;
        st[i] = (gy >= 0 && gy < H && gx >= 0 && gx < W) ? ip[gy * W + gx] : 0.f;
    }
    __syncthreads();

    const int r0 = ty * PX;
    float v[PX + 2][3];
#pragma unroll
    for (int dy = 0; dy < PX + 2; ++dy)
#pragma unroll
        for (int dx = 0; dx < 3; ++dx)
            v[dy][dx] = st[(r0 + dy) * (TW + 2) + tx + dx];

    float acc[PX][COT];
#pragma unroll
    for (int p = 0; p < PX; ++p)
#pragma unroll
        for (int c = 0; c < COT; ++c) acc[p][c] = 0.f;

#pragma unroll
    for (int c = 0; c < COT; ++c) {
        const float* wp2 = ws + c * 9;
#pragma unroll
        for (int kh = 0; kh < 3; ++kh)
#pragma unroll
            for (int kw = 0; kw < 3; ++kw) {
                float wv = wp2[kh * 3 + kw];
#pragma unroll
                for (int p = 0; p < PX; ++p)
                    acc[p][c] += v[p + kh][kw] * wv;
            }
    }

#pragma unroll
    for (int c = 0; c < COT; c += 2) {
        unsigned* op = out + ((size_t)(n * (CO / 2) + (co0 + c) / 2) * H + gy0 + r0) * W
                     + gx0 + tx;
#pragma unroll
        for (int p = 0; p < PX; ++p) {
            float a = fmaxf(acc[p][c], 0.f);
            float b = fmaxf(acc[p][c + 1], 0.f);
            op[(size_t)p * W] = packh(a, b);
        }
    }
}

__global__ void shuffle_relu_k(const float* __restrict__ in, float* __restrict__ out)
{
    int idx = blockIdx.x * blockDim.x + threadIdx.x;
    int x = idx & 1023;
    int y = (idx >> 10) & 1023;
    int n = idx >> 20;
    int c = ((y & 3) << 2) | (x & 3);
    int hh = y >> 2, ww = x >> 2;
    float v = in[(((size_t)(n * 16 + c) * 256) + hh) * 256 + ww];
    out[idx] = v > 0.f ? v : 0.f;
}

extern "C" void kernel_launch(void* const* d_in, const int* in_sizes, int n_in,
                              void* d_out, int out_size)
{
    const float* x   = (const float*)d_in[0];
    const float* we1 = (const float*)d_in[1];
    const float* we2 = (const float*)d_in[2];
    const float* we3 = (const float*)d_in[3];
    const float* wd1 = (const float*)d_in[4];
    const float* wd2 = (const float*)d_in[5];
    const float* wk1 = (const float*)d_in[6];
    const float* wk2 = (const float*)d_in[7];
    const float* wk3 = (const float*)d_in[8];
    const float* wk4 = (const float*)d_in[9];
    float* out = (float*)d_out;

    float *bufA, *bufB, *hbuf;
    uint4* wpack;
    cudaGetSymbolAddress((void**)&bufA, g_bufA);
    cudaGetSymbolAddress((void**)&bufB, g_bufB);
    cudaGetSymbolAddress((void**)&hbuf, g_h);
    cudaGetSymbolAddress((void**)&wpack, g_wpack);
    unsigned* hA = (unsigned*)bufA;
    unsigned* hB = (unsigned*)bufB;

    const int O_E2 = 0, O_E3 = 576, O_D1 = 2880, O_D2 = 5184;
    const int O_K2 = 5760, O_K3 = 8064, O_K4 = 10368;

    // smem = 2*5824*4 (input dbuf) + WTOT*16 (all weights once)
    const int sm_ci16 = 46592 + 9216;    // 55808
    const int sm_ci32 = 46592 + 18432;   // 65024
    const int sm_ci64 = 46592 + 36864;   // 83456
    const int sm_d2   = 46592 + 9216;    // 55808

    cudaFuncSetAttribute(conv3x3_f16<16, 4, 32, 256, 256, true, false>,
                         cudaFuncAttributeMaxDynamicSharedMemorySize, sm_ci16);
    cudaFuncSetAttribute(conv3x3_f16<32, 4, 64, 256, 256, true, false>,
                         cudaFuncAttributeMaxDynamicSharedMemorySize, sm_ci32);
    cudaFuncSetAttribute(conv3x3_f16<64, 4, 32, 256, 256, true, false>,
                         cudaFuncAttributeMaxDynamicSharedMemorySize, sm_ci64);
    cudaFuncSetAttribute(conv3x3_f16<32, 2, 16, 256, 256, false, false>,
                         cudaFuncAttributeMaxDynamicSharedMemorySize, sm_d2);
    cudaFuncSetAttribute(conv3x3_f16<32, 4, 64, 1024, 1024, true, false>,
                         cudaFuncAttributeMaxDynamicSharedMemorySize, sm_ci32);
    cudaFuncSetAttribute(conv3x3_f16<64, 4, 32, 1024, 1024, true, false>,
                         cudaFuncAttributeMaxDynamicSharedMemorySize, sm_ci64);
    cudaFuncSetAttribute(conv3x3_f16<32, 4, 25, 1024, 1024, false, true>,
                         cudaFuncAttributeMaxDynamicSharedMemorySize, sm_ci32);

    const dim3 blk(256);

    prep_all_k<<<45, blk>>>(we2, we3, wd1, wd2, wk2, wk3, wk4, wpack);

    // encoder / decoder @ 256x256 (N=2), 32x16 tiles
    conv3x3_c1_k<16, 4><<<dim3(8, 8, 2), blk>>>(x, we1, hA, 256, 256, 16);
    conv3x3_f16<16, 4, 32, 256, 256, true,  false><<<dim3(8, 16, 2), blk, sm_ci16>>>(hA, wpack + O_E2, hB, nullptr);
    conv3x3_f16<32, 4, 64, 256, 256, true,  false><<<dim3(8, 16, 4), blk, sm_ci32>>>(hB, wpack + O_E3, hA, nullptr);
    conv3x3_f16<64, 4, 32, 256, 256, true,  false><<<dim3(8, 16, 2), blk, sm_ci64>>>(hA, wpack + O_D1, hB, nullptr);
    conv3x3_f16<32, 2, 16, 256, 256, false, false><<<dim3(8, 16, 2), blk, sm_d2>>>(hB, wpack + O_D2, bufA, nullptr);

    // pixel shuffle + relu -> (2,1,1024,1024) fp32
    shuffle_relu_k<<<8192, 256>>>(bufA, hbuf);

    // kernel-prediction branch @ 1024x1024, 32x16 tiles
    conv3x3_c1_k<16, 4><<<dim3(32, 32, 4), blk>>>(hbuf, wk1, hB, 1024, 1024, 32);
    conv3x3_f16<32, 4, 64, 1024, 1024, true,  false><<<dim3(32, 64, 4), blk, sm_ci32>>>(hB, wpack + O_K2, hA, nullptr);
    conv3x3_f16<64, 4, 32, 1024, 1024, true,  false><<<dim3(32, 64, 2), blk, sm_ci64>>>(hA, wpack + O_K3, hB, nullptr);
    // k4 + fused per-pixel 5x5 dynamic conv + residual -> d_out
    conv3x3_f16<32, 4, 25, 1024, 1024, false, true ><<<dim3(32, 64, 2), blk, sm_ci32>>>(hB, wpack + O_K4, out, hbuf);
}

// round 16
// speedup vs baseline: 1.1687x; 1.0188x over previous
#include <cuda_runtime.h>
#include <cuda_fp16.h>
#include <cstddef>

__device__ float g_bufA[134217728];
__device__ float g_bufB[67108864];
__device__ float g_h[2097152];
__device__ uint4 g_wpack[11520];

__device__ __forceinline__ unsigned packh(float lo, float hi) {
    __half2 h = __floats2half2_rn(lo, hi);
    return *reinterpret_cast<unsigned*>(&h);
}

__device__ __forceinline__ void mma_f16(float* c,
                                        unsigned a0, unsigned a1, unsigned a2, unsigned a3,
                                        unsigned b0, unsigned b1) {
    asm volatile("mma.sync.aligned.m16n8k16.row.col.f32.f16.f16.f32 "
                 "{%0,%1,%2,%3}, {%4,%5,%6,%7}, {%8,%9}, {%0,%1,%2,%3};"
                 : "+f"(c[0]), "+f"(c[1]), "+f"(c[2]), "+f"(c[3])
                 : "r"(a0), "r"(a1), "r"(a2), "r"(a3), "r"(b0), "r"(b1));
}

__device__ __forceinline__ void cp_async4(unsigned dst, const void* src, bool ok) {
    int sz = ok ? 4 : 0;
    asm volatile("cp.async.ca.shared.global [%0], [%1], 4, %2;"
                 :: "r"(dst), "l"(src), "r"(sz));
}

__device__ __forceinline__ void cp_async16(unsigned dst, const void* src, bool ok) {
    int sz = ok ? 16 : 0;
    asm volatile("cp.async.cg.shared.global [%0], [%1], 16, %2;"
                 :: "r"(dst), "l"(src), "r"(sz));
}

// Weight prepack: per (group, chunk) blocks of WCNT uint4,
// e = (t*NPAIR + p)*32 + lane. Offsets: e2:0 e3:576 d1:2880 d2:5184 k2:5760
// k3:8064 k4:10368
__global__ void prep_all_k(const float* __restrict__ we2, const float* __restrict__ we3,
                           const float* __restrict__ wd1, const float* __restrict__ wd2,
                           const float* __restrict__ wk2, const float* __restrict__ wk3,
                           const float* __restrict__ wk4, uint4* __restrict__ dst)
{
    int e = blockIdx.x * 256 + threadIdx.x;
    if (e >= 11520) return;
    const float* w; int CI, COT, NT; int rem = e;
    if (rem < 576)                   { w = we2; CI = 16; COT = 32; NT = 4; }
    else if ((rem -= 576)  < 2304)   { w = we3; CI = 32; COT = 64; NT = 4; }
    else if ((rem -= 2304) < 2304)   { w = wd1; CI = 64; COT = 32; NT = 4; }
    else if ((rem -= 2304) < 576)    { w = wd2; CI = 32; COT = 16; NT = 2; }
    else if ((rem -= 576)  < 2304)   { w = wk2; CI = 32; COT = 64; NT = 4; }
    else if ((rem -= 2304) < 2304)   { w = wk3; CI = 64; COT = 32; NT = 4; }
    else       { rem -= 2304;          w = wk4; CI = 32; COT = 25; NT = 4; }

    int NPAIR = NT / 2;
    int WCNT = 9 * NPAIR * 32;
    int NCH = CI / 16;
    int gch = rem / WCNT, r2 = rem % WCNT;
    int g = gch / NCH, ch = gch % NCH;
    int lane = r2 & 31, q = r2 >> 5;
    int p = q % NPAIR, t = q / NPAIR;
    int coa = g * NT * 8 + 2 * p * 8 + (lane >> 2);
    int cob = coa + 8;
    int ci0 = ch * 16 + (lane & 3) * 2;

    auto fetch = [&](int co, int ci) -> float {
        return (co < COT) ? w[(co * CI + ci) * 9 + t] : 0.f;
    };
    uint4 v;
    v.x = packh(fetch(coa, ci0),     fetch(coa, ci0 + 1));
    v.y = packh(fetch(coa, ci0 + 8), fetch(coa, ci0 + 9));
    v.z = packh(fetch(cob, ci0),     fetch(cob, ci0 + 1));
    v.w = packh(fetch(cob, ci0 + 8), fetch(cob, ci0 + 9));
    dst[e] = v;
}

// FP16 tensor-core 3x3 conv + ReLU.  Pixel tile 32(x) x 16(y).
//   Block 256 thr (8 warps); warp w computes output rows w and w+8.
//   Per warp: 4 M-tiles (2 rows x 2 col-halves) x NT N-tiles (8 co).
//   CI chunked by 16 (8 cpair), input + weights double-buffered via cp.async.
//   Smem input: [8 cpair][18 rows][PITCH=40] half2, ICH2=728 (728%32=24 =>
//   conflict-free A loads). Interior at col 4, halo at 3/36.
//   PACKED: half2-pair output; SHUF: d2 -> pixel-shuffled fp32 h (fused);
//   FUSE: k4 -> fused per-pixel 5x5 dynamic conv + residual -> final output.
template <int CI, int NT, int COT, int H, int W, bool PACKED, bool FUSE, bool SHUF>
__global__ __launch_bounds__(256, 2)
void conv3x3_f16(const unsigned* __restrict__ in, const uint4* __restrict__ wp,
                 void* __restrict__ outv, const float* __restrict__ hres)
{
    constexpr int NCH = CI / 16;
    constexpr int PITCH = 40;
    constexpr int ICH2 = 728;                // 18*40 + 8 pad (half2 units)
    constexpr int ISZ = 8 * ICH2;            // 5824 words per buffer
    constexpr int NPAIR = NT / 2;
    constexpr int WCNT = 9 * NPAIR * 32;     // uint4 per chunk
    constexpr int WIT = (WCNT + 255) / 256;
    constexpr int GROUPS = (COT + NT * 8 - 1) / (NT * 8);
    constexpr int ZP = 513;                  // z smem pitch (16*32+1 floats)

    extern __shared__ unsigned smem_u[];
    unsigned* in_s = smem_u;                       // [2][ISZ]
    uint4*    ws   = (uint4*)(smem_u + 2 * ISZ);   // [2][WCNT]

    const int tid  = threadIdx.x;
    const int lane = tid & 31;
    const int wrp  = tid >> 5;
    const int gx0  = blockIdx.x * 32;
    const int gy0  = blockIdx.y * 16;
    const int img  = blockIdx.z / GROUPS;
    const int grp  = blockIdx.z % GROUPS;

    const unsigned in_base = (unsigned)__cvta_generic_to_shared(in_s);
    const unsigned ws_base = (unsigned)__cvta_generic_to_shared(ws);

    auto fill = [&](int ch, int buf) {
        const unsigned* base = in + ((size_t)img * (CI / 2) + ch * 8) * H * W;
        const unsigned sbase = in_base + buf * (ISZ * 4);
        // interior: 8 cpair x 18 rows x 8 segs(16B) = 1152
#pragma unroll
        for (int j = 0; j < 5; ++j) {
            int idx = tid + j * 256;
            if (idx < 1152) {
                int ci = idx / 144;
                int rem = idx % 144;
                int r = rem >> 3, seg = rem & 7;
                int gy = gy0 + r - 1;
                bool ok = (unsigned)gy < (unsigned)H;
                const unsigned* src = base + (size_t)ci * H * W
                                    + (ok ? gy : 0) * W + gx0 + seg * 4;
                unsigned dst = sbase + (ci * ICH2 + r * PITCH + 4 + seg * 4) * 4;
                cp_async16(dst, src, ok);
            }
        }
        // halo: 8 cpair x 18 rows x 2 sides = 288 scalar half2
#pragma unroll
        for (int j = 0; j < 2; ++j) {
            int idx = tid + j * 256;
            if (idx < 288) {
                int ci = idx / 36;
                int rem = idx % 36;
                int r = rem >> 1, side = rem & 1;
                int gy = gy0 + r - 1;
                int gx = side ? gx0 + 32 : gx0 - 1;
                bool ok = ((unsigned)gy < (unsigned)H) && ((unsigned)gx < (unsigned)W);
                const unsigned* src = base + (size_t)ci * H * W + (ok ? gy * W + gx : 0);
                unsigned dst = sbase + (ci * ICH2 + r * PITCH + (side ? 36 : 3)) * 4;
                cp_async4(dst, src, ok);
            }
        }
        // weights: linear 16B copies of prepacked fragments
        const uint4* wsrc = wp + ((size_t)grp * NCH + ch) * WCNT;
        const unsigned wdst = ws_base + buf * WCNT * 16;
#pragma unroll
        for (int j = 0; j < WIT; ++j) {
            int i = tid + j * 256;
            if (i < WCNT)
                cp_async16(wdst + i * 16, wsrc + i, true);
        }
        asm volatile("cp.async.commit_group;");
    };

    float acc[2][2][NT][4];   // [row-half][col-half][ntile][frag]
#pragma unroll
    for (int mr = 0; mr < 2; ++mr)
#pragma unroll
        for (int m = 0; m < 2; ++m)
#pragma unroll
            for (int n = 0; n < NT; ++n)
#pragma unroll
                for (int i = 0; i < 4; ++i) acc[mr][m][n][i] = 0.f;

    fill(0, 0);
    asm volatile("cp.async.wait_group 0;");
    __syncthreads();

    const int arow = lane >> 2;
    const int aci  = lane & 3;

    for (int ch = 0; ch < NCH; ++ch) {
        const int buf = ch & 1;
        if (ch + 1 < NCH) fill(ch + 1, buf ^ 1);

        const unsigned* A = in_s + buf * ISZ;
        const uint4*    B = ws + buf * WCNT;
#pragma unroll
        for (int kh = 0; kh < 3; ++kh) {
#pragma unroll
            for (int kw = 0; kw < 3; ++kw) {
                const int t = kh * 3 + kw;
                const uint4* wb = B + t * NPAIR * 32 + lane;
#pragma unroll
                for (int mr = 0; mr < 2; ++mr) {
                    const int off = (wrp + mr * 8 + kh) * PITCH + 3 + kw + arow;
                    unsigned a00 = A[aci * ICH2 + off];
                    unsigned a01 = A[aci * ICH2 + off + 8];
                    unsigned a02 = A[(aci + 4) * ICH2 + off];
                    unsigned a03 = A[(aci + 4) * ICH2 + off + 8];
                    unsigned a10 = A[aci * ICH2 + off + 16];
                    unsigned a11 = A[aci * ICH2 + off + 24];
                    unsigned a12 = A[(aci + 4) * ICH2 + off + 16];
                    unsigned a13 = A[(aci + 4) * ICH2 + off + 24];
#pragma unroll
                    for (int p = 0; p < NPAIR; ++p) {
                        uint4 b = wb[p * 32];
                        mma_f16(acc[mr][0][2 * p],     a00, a01, a02, a03, b.x, b.y);
                        mma_f16(acc[mr][1][2 * p],     a10, a11, a12, a13, b.x, b.y);
                        mma_f16(acc[mr][0][2 * p + 1], a00, a01, a02, a03, b.z, b.w);
                        mma_f16(acc[mr][1][2 * p + 1], a10, a11, a12, a13, b.z, b.w);
                    }
                }
            }
        }

        if (ch + 1 < NCH) {
            asm volatile("cp.async.wait_group 0;");
            __syncthreads();
        }
    }

    if (FUSE) {
        // -------- fused per-pixel 5x5 dynamic conv + residual (k4) --------
        __syncthreads();
        float* z_s = (float*)smem_u;          // [25][ZP]
        float* h_s = z_s + 25 * ZP;           // [20][36]

#pragma unroll
        for (int mr = 0; mr < 2; ++mr) {
            const int y = wrp + mr * 8;
#pragma unroll
            for (int m = 0; m < 2; ++m) {
                const int xl = m * 16 + arow;
#pragma unroll
                for (int n = 0; n < NT; ++n) {
                    const int coA = n * 8 + 2 * (lane & 3);
                    float v0 = fmaxf(acc[mr][m][n][0], 0.f);
                    float v1 = fmaxf(acc[mr][m][n][1], 0.f);
                    float v2 = fmaxf(acc[mr][m][n][2], 0.f);
                    float v3 = fmaxf(acc[mr][m][n][3], 0.f);
                    if (coA < 25) {
                        z_s[coA * ZP + y * 32 + xl]     = v0;
                        z_s[coA * ZP + y * 32 + xl + 8] = v2;
                    }
                    if (coA + 1 < 25) {
                        z_s[(coA + 1) * ZP + y * 32 + xl]     = v1;
                        z_s[(coA + 1) * ZP + y * 32 + xl + 8] = v3;
                    }
                }
            }
        }
        const float* hp = hres + (size_t)img * H * W;
        for (int i = tid; i < 20 * 36; i += 256) {
            int r = i / 36, c = i % 36;
            int gy = gy0 + r - 2, gx = gx0 + c - 2;
            h_s[i] = ((unsigned)gy < (unsigned)H && (unsigned)gx < (unsigned)W)
                     ? hp[gy * W + gx] : 0.f;
        }
        __syncthreads();

        const int py = tid >> 5, px = tid & 31;
        float* o = (float*)outv;
#pragma unroll
        for (int mr = 0; mr < 2; ++mr) {
            const int yy = py + mr * 8;
            float res = h_s[(yy + 2) * 36 + px + 2];   // residual h
#pragma unroll
            for (int j = 0; j < 25; ++j) {
                const int kwv = j / 5, khv = j % 5;
                res += h_s[(yy + khv) * 36 + px + kwv] * z_s[j * ZP + yy * 32 + px];
            }
            o[(size_t)img * H * W + (size_t)(gy0 + yy) * W + gx0 + px] = res;
        }
        return;
    }

    // ---- epilogue: ReLU + store ----
#pragma unroll
    for (int mr = 0; mr < 2; ++mr) {
        const int y = gy0 + wrp + mr * 8;
#pragma unroll
        for (int m = 0; m < 2; ++m) {
            const int x0 = gx0 + m * 16 + arow;
#pragma unroll
            for (int n = 0; n < NT; ++n) {
                const int coA = grp * NT * 8 + n * 8 + 2 * (lane & 3);
                float v0 = fmaxf(acc[mr][m][n][0], 0.f);
                float v1 = fmaxf(acc[mr][m][n][1], 0.f);
                float v2 = fmaxf(acc[mr][m][n][2], 0.f);
                float v3 = fmaxf(acc[mr][m][n][3], 0.f);
                if (SHUF) {
                    // fused PixelShuffle(4): h[4y+(c>>2)][4x+(c&3)] = v
                    float* o = (float*)outv;
                    float* ob = o + (size_t)img * 1048576;
                    ob[(size_t)(4 * y + (coA >> 2)) * 1024 + 4 * x0 + (coA & 3)] = v0;
                    ob[(size_t)(4 * y + ((coA + 1) >> 2)) * 1024 + 4 * x0 + ((coA + 1) & 3)] = v1;
                    ob[(size_t)(4 * y + (coA >> 2)) * 1024 + 4 * (x0 + 8) + (coA & 3)] = v2;
                    ob[(size_t)(4 * y + ((coA + 1) >> 2)) * 1024 + 4 * (x0 + 8) + ((coA + 1) & 3)] = v3;
                } else if (PACKED) {
                    unsigned* o = (unsigned*)outv;
                    unsigned* p = o + ((size_t)(img * (COT / 2) + (coA >> 1)) * H + y) * W;
                    p[x0]     = packh(v0, v1);
                    p[x0 + 8] = packh(v2, v3);
                } else {
                    float* o = (float*)outv;
                    if (coA < COT) {
                        float* p = o + ((size_t)(img * COT + coA) * H + y) * W;
                        p[x0]     = v0;
                        p[x0 + 8] = v2;
                    }
                    if (coA + 1 < COT) {
                        float* p = o + ((size_t)(img * COT + coA + 1) * H + y) * W;
                        p[x0]     = v1;
                        p[x0 + 8] = v3;
                    }
                }
            }
        }
    }
}

// fp32 3x3 conv + ReLU for CI=1 layers (e1, k1); writes packed half2 pairs.
template <int COT, int PX>
__global__ __launch_bounds__(256)
void conv3x3_c1_k(const float* __restrict__ in, const float* __restrict__ w,
                  unsigned* __restrict__ out, int H, int W, int CO)
{
    constexpr int TW = 32;
    constexpr int TH = 8 * PX;
    __shared__ float st[(TH + 2) * (TW + 2)];
    __shared__ float ws[COT * 9];

    const int tid = threadIdx.x;
    const int tx = tid & 31;
    const int ty = tid >> 5;

    const int groups = CO / COT;
    const int g  = blockIdx.z % groups;
    const int n  = blockIdx.z / groups;
    const int co0 = g * COT;

    if (tid < COT * 9) ws[tid] = w[co0 * 9 + tid];

    const int gx0 = blockIdx.x * TW;
    const int gy0 = blockIdx.y * TH;

    const float* ip = in + (size_t)n * H * W;
    for (int i = tid; i < (TH + 2) * (TW + 2); i += 256) {
        int r = i / (TW + 2), c = i % (TW + 2);
        int gy = gy0 + r - 1, gx = gx0 + c - 1;
        st[i] = (gy >= 0 && gy < H && gx >= 0 && gx < W) ? ip[gy * W + gx] : 0.f;
    }
    __syncthreads();

    const int r0 = ty * PX;
    float v[PX + 2][3];
#pragma unroll
    for (int dy = 0; dy < PX + 2; ++dy)
#pragma unroll
        for (int dx = 0; dx < 3; ++dx)
            v[dy][dx] = st[(r0 + dy) * (TW + 2) + tx + dx];

    float acc[PX][COT];
#pragma unroll
    for (int p = 0; p < PX; ++p)
#pragma unroll
        for (int c = 0; c < COT; ++c) acc[p][c] = 0.f;

#pragma unroll
    for (int c = 0; c < COT; ++c) {
        const float* wp2 = ws + c * 9;
#pragma unroll
        for (int kh = 0; kh < 3; ++kh)
#pragma unroll
            for (int kw = 0; kw < 3; ++kw) {
                float wv = wp2[kh * 3 + kw];
#pragma unroll
                for (int p = 0; p < PX; ++p)
                    acc[p][c] += v[p + kh][kw] * wv;
            }
    }

#pragma unroll
    for (int c = 0; c < COT; c += 2) {
        unsigned* op = out + ((size_t)(n * (CO / 2) + (co0 + c) / 2) * H + gy0 + r0) * W
                     + gx0 + tx;
#pragma unroll
        for (int p = 0; p < PX; ++p) {
            float a = fmaxf(acc[p][c], 0.f);
            float b = fmaxf(acc[p][c + 1], 0.f);
            op[(size_t)p * W] = packh(a, b);
        }
    }
}

extern "C" void kernel_launch(void* const* d_in, const int* in_sizes, int n_in,
                              void* d_out, int out_size)
{
    const float* x   = (const float*)d_in[0];
    const float* we1 = (const float*)d_in[1];
    const float* we2 = (const float*)d_in[2];
    const float* we3 = (const float*)d_in[3];
    const float* wd1 = (const float*)d_in[4];
    const float* wd2 = (const float*)d_in[5];
    const float* wk1 = (const float*)d_in[6];
    const float* wk2 = (const float*)d_in[7];
    const float* wk3 = (const float*)d_in[8];
    const float* wk4 = (const float*)d_in[9];
    float* out = (float*)d_out;

    float *bufA, *bufB, *hbuf;
    uint4* wpack;
    cudaGetSymbolAddress((void**)&bufA, g_bufA);
    cudaGetSymbolAddress((void**)&bufB, g_bufB);
    cudaGetSymbolAddress((void**)&hbuf, g_h);
    cudaGetSymbolAddress((void**)&wpack, g_wpack);
    unsigned* hA = (unsigned*)bufA;
    unsigned* hB = (unsigned*)bufB;

    const int O_E2 = 0, O_E3 = 576, O_D1 = 2880, O_D2 = 5184;
    const int O_K2 = 5760, O_K3 = 8064, O_K4 = 10368;

    // smem: 2*5824*4 (input) + 2*WCNT*16 (weights)
    const int sm_nt4 = 2 * 5824 * 4 + 2 * 576 * 16;   // 65024
    const int sm_nt2 = 2 * 5824 * 4 + 2 * 288 * 16;   // 55808

    //                              CI NT COT    H     W  PACKED FUSE  SHUF
    cudaFuncSetAttribute(conv3x3_f16<16, 4, 32, 256, 256, true, false, false>,
                         cudaFuncAttributeMaxDynamicSharedMemorySize, sm_nt4);
    cudaFuncSetAttribute(conv3x3_f16<32, 4, 64, 256, 256, true, false, false>,
                         cudaFuncAttributeMaxDynamicSharedMemorySize, sm_nt4);
    cudaFuncSetAttribute(conv3x3_f16<64, 4, 32, 256, 256, true, false, false>,
                         cudaFuncAttributeMaxDynamicSharedMemorySize, sm_nt4);
    cudaFuncSetAttribute(conv3x3_f16<32, 2, 16, 256, 256, false, false, true>,
                         cudaFuncAttributeMaxDynamicSharedMemorySize, sm_nt2);
    cudaFuncSetAttribute(conv3x3_f16<32, 4, 64, 1024, 1024, true, false, false>,
                         cudaFuncAttributeMaxDynamicSharedMemorySize, sm_nt4);
    cudaFuncSetAttribute(conv3x3_f16<64, 4, 32, 1024, 1024, true, false, false>,
                         cudaFuncAttributeMaxDynamicSharedMemorySize, sm_nt4);
    cudaFuncSetAttribute(conv3x3_f16<32, 4, 25, 1024, 1024, false, true, false>,
                         cudaFuncAttributeMaxDynamicSharedMemorySize, sm_nt4);

    const dim3 blk(256);

    // ---- weight prepack: one launch for all 7 layers ----
    prep_all_k<<<45, blk>>>(we2, we3, wd1, wd2, wk2, wk3, wk4, wpack);

    // ---- encoder / decoder @ 256x256 (N=2), 32x16 tiles ----
    conv3x3_c1_k<16, 4><<<dim3(8, 8, 2), blk>>>(x, we1, hA, 256, 256, 16);
    conv3x3_f16<16, 4, 32, 256, 256, true,  false, false><<<dim3(8, 16, 2), blk, sm_nt4>>>(hA, wpack + O_E2, hB, nullptr);
    conv3x3_f16<32, 4, 64, 256, 256, true,  false, false><<<dim3(8, 16, 4), blk, sm_nt4>>>(hB, wpack + O_E3, hA, nullptr);
    conv3x3_f16<64, 4, 32, 256, 256, true,  false, false><<<dim3(8, 16, 2), blk, sm_nt4>>>(hA, wpack + O_D1, hB, nullptr);
    // d2 with FUSED PixelShuffle(4) + ReLU -> hbuf (2,1,1024,1024) fp32
    conv3x3_f16<32, 2, 16, 256, 256, false, false, true ><<<dim3(8, 16, 2), blk, sm_nt2>>>(hB, wpack + O_D2, hbuf, nullptr);

    // ---- kernel-prediction branch @ 1024x1024, 32x16 tiles ----
    conv3x3_c1_k<16, 4><<<dim3(32, 32, 4), blk>>>(hbuf, wk1, hB, 1024, 1024, 32);
    conv3x3_f16<32, 4, 64, 1024, 1024, true,  false, false><<<dim3(32, 64, 4), blk, sm_nt4>>>(hB, wpack + O_K2, hA, nullptr);
    conv3x3_f16<64, 4, 32, 1024, 1024, true,  false, false><<<dim3(32, 64, 2), blk, sm_nt4>>>(hA, wpack + O_K3, hB, nullptr);
    // k4 fused with per-pixel 5x5 dynamic conv + residual: writes d_out directly
    conv3x3_f16<32, 4, 25, 1024, 1024, false, true,  false><<<dim3(32, 64, 2), blk, sm_nt4>>>(hB, wpack + O_K4, out, hbuf);
}